// round 8
// baseline (speedup 1.0000x reference)
#include <cuda_runtime.h>
#include <math.h>
#include <stdint.h>

// Fixed problem shapes
#define HOP 256
#define NFFT 2048
#define MH 1024
#define NPITCH 256
#define BATCH 16
#define NSAMP 480000
#define TFRAMES 1876
#define KU 103            // SPX bins 0..102
#define KLA 102           // LA bins 0..101
#define LPAD 168          // zero-pad in front of LS (max shift 165)

struct Params {
    int   closest[NPITCH];
    int   shift[8];
    float wgt[8];
};

// Phase A/B layout padding (conflict-free for strides 1 and 64)
__device__ __forceinline__ int PHYS(int i) { return i + 4 * (i >> 6); }

__device__ __forceinline__ void bfly4(
    float& r0, float& i0, float& r1, float& i1,
    float& r2, float& i2, float& r3, float& i3,
    float c1, float s1, float c2, float s2, float c3, float s3)
{
    float t0r = r0 + r2, t0i = i0 + i2;
    float t1r = r1 + r3, t1i = i1 + i3;
    float t2r = r0 - r2, t2i = i0 - i2;
    float t3r = r1 - r3, t3i = i1 - i3;
    float y0r = t0r + t1r, y0i = t0i + t1i;
    float y2r = t0r - t1r, y2i = t0i - t1i;
    float y1r = t2r + t3i, y1i = t2i - t3r;
    float y3r = t2r - t3i, y3i = t2i + t3r;
    r0 = y0r;                 i0 = y0i;
    r1 = y1r * c1 - y1i * s1; i1 = y1r * s1 + y1i * c1;
    r2 = y2r * c2 - y2i * s2; i2 = y2r * s2 + y2i * c2;
    r3 = y3r * c3 - y3i * s3; i3 = y3r * s3 + y3i * c3;
}

#define CA 0.9238795325112867f
#define CB 0.3826834323650898f
#define CR 0.7071067811865476f

__global__ __launch_bounds__(64)
void pitch_kernel(const float* __restrict__ wav, float* __restrict__ out, Params p)
{
    __shared__ __align__(16) float2 Z[1084];          // A->B exchange (PHYS layout)
    __shared__ __align__(16) float2 F0[KU];           // final FFT bins 0..102 (y0)
    __shared__ __align__(16) float2 F1[102];          // final FFT bins 922..1023 (y3); F1[m]=bin 922+m
    __shared__ __align__(16) float2 SPX[KU];          // unpacked raw rfft bins 0..102
    __shared__ __align__(16) float  LA[104];          // log mag (102,103 zero)
    __shared__ __align__(16) float  CS1[104];         // inclusive prefix sums of LA
    __shared__ __align__(16) float  LSB[LPAD + NPITCH];
    __shared__ float RED[2];

    const int tid = threadIdx.x;     // 0..63
    const int t   = blockIdx.x;
    const int b   = blockIdx.y;
    const float* w = wav + (size_t)b * NSAMP;
    const int base = t * HOP - (NFFT / 2);

    // zero LS front padding (consumed much later, after several barriers)
    if (tid < LPAD / 4)
        reinterpret_cast<float4*>(LSB)[tid] = make_float4(0.f, 0.f, 0.f, 0.f);

    // ================= Phase A: load + stages d4,d3 in regs ======================
    float er[16], ei[16];
    if (base >= 0 && base + NFFT <= NSAMP) {
        const float2* src = reinterpret_cast<const float2*>(w + base);
        #pragma unroll
        for (int k = 0; k < 16; ++k) {
            float2 xv = src[tid + 64 * k];
            er[k] = xv.x; ei[k] = xv.y;
        }
    } else {
        #pragma unroll
        for (int k = 0; k < 16; ++k) {
            int n  = tid + 64 * k;
            int p0 = base + 2 * n, p1 = p0 + 1;
            p0 = p0 < 0 ? -p0 : (p0 >= NSAMP ? 2 * NSAMP - 2 - p0 : p0);
            p1 = p1 < 0 ? -p1 : (p1 >= NSAMP ? 2 * NSAMP - 2 - p1 : p1);
            er[k] = w[p0]; ei[k] = w[p1];
        }
    }

    {
        float c1, s1; __sincosf((float)tid * (-6.283185307179586f / 1024.0f), &s1, &c1);
        float c2 = c1 * c1 - s1 * s1, s2 = 2.0f * c1 * s1;
        float c3 = c1 * c2 - s1 * s2, s3 = c1 * s2 + s1 * c2;
        bfly4(er[0], ei[0], er[4], ei[4], er[8], ei[8], er[12], ei[12],
              c1, s1, c2, s2, c3, s3);
        bfly4(er[1], ei[1], er[5], ei[5], er[9], ei[9], er[13], ei[13],
              c1 * CA + s1 * CB, s1 * CA - c1 * CB,
              (c2 + s2) * CR,    (s2 - c2) * CR,
              c3 * CB + s3 * CA, s3 * CB - c3 * CA);
        bfly4(er[2], ei[2], er[6], ei[6], er[10], ei[10], er[14], ei[14],
              (c1 + s1) * CR, (s1 - c1) * CR,
              s2,            -c2,
              (s3 - c3) * CR, -(c3 + s3) * CR);
        bfly4(er[3], ei[3], er[7], ei[7], er[11], ei[11], er[15], ei[15],
              c1 * CB + s1 * CA, s1 * CB - c1 * CA,
              (s2 - c2) * CR,   -(c2 + s2) * CR,
              -c3 * CA - s3 * CB, c3 * CB - s3 * CA);

        float vc1 = c2 * c2 - s2 * s2, vs1 = 2.0f * c2 * s2;
        float vc2 = vc1 * vc1 - vs1 * vs1, vs2 = 2.0f * vc1 * vs1;
        float vc3 = vc1 * vc2 - vs1 * vs2, vs3 = vc1 * vs2 + vs1 * vc2;
        #pragma unroll
        for (int b2 = 0; b2 < 4; ++b2)
            bfly4(er[4 * b2], ei[4 * b2], er[4 * b2 + 1], ei[4 * b2 + 1],
                  er[4 * b2 + 2], ei[4 * b2 + 2], er[4 * b2 + 3], ei[4 * b2 + 3],
                  vc1, vs1, vc2, vs2, vc3, vs3);
    }
    #pragma unroll
    for (int k = 0; k < 16; ++k)
        Z[PHYS(tid + 64 * k)] = make_float2(er[k], ei[k]);
    __syncthreads();

    // ====== Phase B: stages d2,d1 in regs + final d0 stage via quad shuffles =====
    {
        const int H  = tid >> 2;
        const int d0 = tid & 3;
        const int h  = 4 * (H & 3) + (H >> 2);
        float fr[16], fi[16];     // index 4*d2 + d1
        #pragma unroll
        for (int d2 = 0; d2 < 4; ++d2)
            #pragma unroll
            for (int d1 = 0; d1 < 4; ++d1) {
                float2 v = Z[PHYS(64 * H + 16 * d2 + 4 * d1 + d0)];
                fr[4 * d2 + d1] = v.x; fi[4 * d2 + d1] = v.y;
            }

        float uc1, us1; __sincosf((float)d0 * (-6.283185307179586f / 64.0f), &us1, &uc1);

        #pragma unroll
        for (int d1 = 0; d1 < 4; ++d1) {
            float bc1, bs1;
            if (d1 == 0)      { bc1 = uc1; bs1 = us1; }
            else if (d1 == 1) { bc1 = uc1 * CA + us1 * CB; bs1 = us1 * CA - uc1 * CB; }
            else if (d1 == 2) { bc1 = (uc1 + us1) * CR;    bs1 = (us1 - uc1) * CR; }
            else              { bc1 = uc1 * CB + us1 * CA; bs1 = us1 * CB - uc1 * CA; }
            float bc2 = bc1 * bc1 - bs1 * bs1, bs2 = 2.0f * bc1 * bs1;
            float bc3 = bc1 * bc2 - bs1 * bs2, bs3 = bc1 * bs2 + bs1 * bc2;
            bfly4(fr[d1], fi[d1], fr[4 + d1], fi[4 + d1],
                  fr[8 + d1], fi[8 + d1], fr[12 + d1], fi[12 + d1],
                  bc1, bs1, bc2, bs2, bc3, bs3);
        }
        {
            float q2c = uc1 * uc1 - us1 * us1, q2s = 2.0f * uc1 * us1;
            float tc1 = q2c * q2c - q2s * q2s, ts1 = 2.0f * q2c * q2s;
            float tc2 = tc1 * tc1 - ts1 * ts1, ts2 = 2.0f * tc1 * ts1;
            float tc3 = tc1 * tc2 - ts1 * ts2, ts3 = tc1 * ts2 + ts1 * tc2;
            #pragma unroll
            for (int d2 = 0; d2 < 4; ++d2)
                bfly4(fr[4 * d2], fi[4 * d2], fr[4 * d2 + 1], fi[4 * d2 + 1],
                      fr[4 * d2 + 2], fi[4 * d2 + 2], fr[4 * d2 + 3], fi[4 * d2 + 3],
                      tc1, ts1, tc2, ts2, tc3, ts3);
        }

        // ---- final stage (no twiddles) across d0 within each quad, via shuffles.
        // Quad lanes d0=0..3 hold elements c=0..3 of the same rows r = 16W + h,
        // W = 4*d1+d2 (register index 4*d2+d1 = 4*(W&3)+(W>>2)).
        // Need y0 for r<=102 (W<=6) and y3 -> bin 768+r for r>=154 (W>=9).
        const unsigned FM = 0xffffffffu;
        #pragma unroll
        for (int W = 0; W < 16; ++W) {
            if (W == 7 || W == 8) continue;
            const int idx = 4 * (W & 3) + (W >> 2);
            float vr = fr[idx], vi = fi[idx];
            if (W <= 6) {
                float sr = vr + __shfl_xor_sync(FM, vr, 2);
                float si = vi + __shfl_xor_sync(FM, vi, 2);
                sr += __shfl_xor_sync(FM, sr, 1);
                si += __shfl_xor_sync(FM, si, 1);
                if (d0 == (W & 3) && (W < 6 || h <= 6))
                    F0[16 * W + h] = make_float2(sr, si);
            } else {
                float ur = __shfl_xor_sync(FM, vr, 2);
                float ui = __shfl_xor_sync(FM, vi, 2);
                float tr = (d0 < 2) ? (vr - ur) : (ur - vr);   // even lanes: t2, odd: t3
                float ti = (d0 < 2) ? (vi - ui) : (ui - vi);
                float pr = __shfl_xor_sync(FM, tr, 1);
                float pi = __shfl_xor_sync(FM, ti, 1);
                float y3r, y3i;
                if ((d0 & 1) == 0) { y3r = tr - pi; y3i = ti + pr; }
                else               { y3r = pr - ti; y3i = pi + tr; }
                if (d0 == (W & 3) && (W > 9 || h >= 10))
                    F1[16 * W + h - 154] = make_float2(y3r, y3i);   // bin 768+r = 922+m
            }
        }
    }
    __syncthreads();

    // ================= unpack rfft bins 0..102 from F0/F1 ========================
    #pragma unroll
    for (int it = 0; it < 2; ++it) {
        int k = tid + 64 * it;
        if (k < KU) {
            float2 A  = F0[k];
            float2 Bv = (k == 0) ? A : F1[102 - k];    // bin 1024-k = 922 + (102-k)
            float zer =  0.5f * (A.x + Bv.x);
            float zei =  0.5f * (A.y - Bv.y);
            float zor =  0.5f * (A.y + Bv.y);
            float zoi = -0.5f * (A.x - Bv.x);
            float sn, cs;
            __sincosf((float)k * (-3.141592653589793f / 1024.0f), &sn, &cs);
            SPX[k] = make_float2(zer + cs * zor - sn * zoi,
                                 zei + cs * zoi + sn * zor);
        }
    }
    __syncthreads();

    // ====== window as spectral conv: Xw = 0.5 X[k] - 0.25(X[k-1]+X[k+1]) ========
    #pragma unroll
    for (int it = 0; it < 2; ++it) {
        int k = tid + 64 * it;
        if (k < KLA) {
            float2 Xc = SPX[k];
            float2 Xp = SPX[k + 1];
            float2 Xm = (k == 0) ? make_float2(SPX[1].x, -SPX[1].y) : SPX[k - 1];
            float xr = 0.5f * Xc.x - 0.25f * (Xm.x + Xp.x);
            float xi = 0.5f * Xc.y - 0.25f * (Xm.y + Xp.y);
            LA[k] = __logf(sqrtf(xr * xr + xi * xi) + 1e-8f);
        }
    }
    if (tid < 2) LA[KLA + tid] = 0.f;
    __syncthreads();

    // ================= single-pass scan (warp 0): CS1 inclusive ==================
    if (tid < 32) {
        float v0 = 0.f, v1 = 0.f, v2 = 0.f, v3 = 0.f;
        if (tid < 26) {
            float4 q = reinterpret_cast<const float4*>(LA)[tid];
            v0 = q.x; v1 = q.y; v2 = q.z; v3 = q.w;
        }
        float p1 = v0 + v1, p2 = p1 + v2, p3 = p2 + v3;
        float s = p3;
        #pragma unroll
        for (int o = 1; o < 32; o <<= 1) {
            float u = __shfl_up_sync(0xffffffffu, s, o);
            if (tid >= o) s += u;
        }
        float excl = s - p3;
        if (tid < 26)
            reinterpret_cast<float4*>(CS1)[tid] =
                make_float4(excl + v0, excl + p1, excl + p2, excl + p3);
    }
    __syncthreads();

    // ============ fine structure: 4 consecutive pitch bins per thread ============
    float lsv[4];
    {
        int4 c4 = reinterpret_cast<const int4*>(p.closest)[tid];
        int cis[4] = {c4.x, c4.y, c4.z, c4.w};
        float LA0 = LA[0];
        #pragma unroll
        for (int j = 0; j < 4; ++j) {
            int ci = cis[j];                  // 3..85
            int lo = ci - 15, hi = ci + 16;   // hi <= 101
            float sum = (lo <= 0) ? fmaf((float)(-lo), LA0, CS1[hi])
                                  : CS1[hi] - CS1[lo - 1];
            lsv[j] = __expf(LA[ci] - sum * 0.03125f);
        }
        *reinterpret_cast<float4*>(&LSB[LPAD + 4 * tid]) =
            make_float4(lsv[0], lsv[1], lsv[2], lsv[3]);
    }
    __syncthreads();

    // ================= subharmonic summation (zero-padded, guard-free) ==========
    float acc[4] = {lsv[0], lsv[1], lsv[2], lsv[3]};
    #pragma unroll
    for (int n = 1; n < 8; ++n) {
        int   sh = p.shift[n];
        float wn = p.wgt[n];
        int   bi = LPAD + 4 * tid - sh;       // >= 3 always
        if ((sh & 3) == 0) {
            float4 q = *reinterpret_cast<const float4*>(&LSB[bi]);
            acc[0] = fmaf(wn, q.x, acc[0]);
            acc[1] = fmaf(wn, q.y, acc[1]);
            acc[2] = fmaf(wn, q.z, acc[2]);
            acc[3] = fmaf(wn, q.w, acc[3]);
        } else if ((sh & 1) == 0) {
            float2 qa = *reinterpret_cast<const float2*>(&LSB[bi]);
            float2 qb = *reinterpret_cast<const float2*>(&LSB[bi + 2]);
            acc[0] = fmaf(wn, qa.x, acc[0]);
            acc[1] = fmaf(wn, qa.y, acc[1]);
            acc[2] = fmaf(wn, qb.x, acc[2]);
            acc[3] = fmaf(wn, qb.y, acc[3]);
        } else {
            #pragma unroll
            for (int j = 0; j < 4; ++j)
                acc[j] = fmaf(wn, LSB[bi + j], acc[j]);
        }
    }

    // ================= per-frame max, normalize, store ===========================
    float mloc = fmaxf(fmaxf(acc[0], acc[1]), fmaxf(acc[2], acc[3]));
    #pragma unroll
    for (int o = 16; o; o >>= 1)
        mloc = fmaxf(mloc, __shfl_xor_sync(0xffffffffu, mloc, o));
    if ((tid & 31) == 0) RED[tid >> 5] = mloc;
    __syncthreads();
    float mx = fmaxf(fmaxf(RED[0], RED[1]), 1e-8f);

    float4 o4;
    o4.x = __fdividef(acc[0], mx);
    o4.y = __fdividef(acc[1], mx);
    o4.z = __fdividef(acc[2], mx);
    o4.w = __fdividef(acc[3], mx);
    reinterpret_cast<float4*>(out + ((size_t)b * TFRAMES + t) * NPITCH)[tid] = o4;
}

extern "C" void kernel_launch(void* const* d_in, const int* in_sizes, int n_in,
                              void* d_out, int out_size)
{
    (void)in_sizes; (void)n_in; (void)out_size;
    const float* wav = (const float*)d_in[0];
    float* out = (float*)d_out;

    Params p;

    // Gather indices: f32 argmin over |linspace(0,12000,1025) - center_freq|
    const double l40 = log(40.0), l1000 = log(1000.0);
    for (int j = 0; j < NPITCH; ++j) {
        double cd = exp(l40 + (double)j * (l1000 - l40) / 255.0);
        float  cf = (float)cd;
        const float step = 11.71875f;
        int i0 = (int)(cd / 11.71875);
        int best = 0; float bestd = 3.4e38f;
        for (int i = i0 - 2; i <= i0 + 2; ++i) {
            int ic = i < 0 ? 0 : (i > 1024 ? 1024 : i);
            float d = fabsf((float)ic * step - cf);
            if (d < bestd) { bestd = d; best = ic; }
        }
        p.closest[j] = best;
    }

    // Harmonic shifts: Python round() == rint (half-even), identical expression
    const double cpb = 1200.0 * log2(25.0) / 255.0;
    p.shift[0] = 0; p.wgt[0] = 1.0f;
    for (int n = 2; n <= 8; ++n) {
        p.shift[n - 1] = (int)rint(1200.0 * log2((double)n) / cpb);
        p.wgt[n - 1]   = (float)pow(0.86, (double)(n - 1));
    }

    dim3 grid(TFRAMES, BATCH);
    pitch_kernel<<<grid, 64>>>(wav, out, p);
}

// round 9
// speedup vs baseline: 1.0630x; 1.0630x over previous
#include <cuda_runtime.h>
#include <math.h>
#include <stdint.h>

// Fixed problem shapes
#define HOP 256
#define NFFT 2048
#define MH 1024
#define NPITCH 256
#define BATCH 16
#define NSAMP 480000
#define TFRAMES 1876
#define KU 103            // SPX bins 0..102
#define KLA 102           // LA bins 0..101
#define LPAD 168          // zero-pad in front of LS (max shift 165)

struct Params {
    int   closest[NPITCH];
    int   shift[8];
    float wgt[8];
};

// Phase A/B layout padding (conflict-free for strides 1 and 64)
__device__ __forceinline__ int PHYS(int i) { return i + 4 * (i >> 6); }
// Phase B-out / C-in: element c of final-butterfly row r at 277*c + r + (r>>4)
__device__ __forceinline__ int QROW(int r) { return r + (r >> 4); }

__device__ __forceinline__ void bfly4(
    float& r0, float& i0, float& r1, float& i1,
    float& r2, float& i2, float& r3, float& i3,
    float c1, float s1, float c2, float s2, float c3, float s3)
{
    float t0r = r0 + r2, t0i = i0 + i2;
    float t1r = r1 + r3, t1i = i1 + i3;
    float t2r = r0 - r2, t2i = i0 - i2;
    float t3r = r1 - r3, t3i = i1 - i3;
    float y0r = t0r + t1r, y0i = t0i + t1i;
    float y2r = t0r - t1r, y2i = t0i - t1i;
    float y1r = t2r + t3i, y1i = t2i - t3r;
    float y3r = t2r - t3i, y3i = t2i + t3r;
    r0 = y0r;                 i0 = y0i;
    r1 = y1r * c1 - y1i * s1; i1 = y1r * s1 + y1i * c1;
    r2 = y2r * c2 - y2i * s2; i2 = y2r * s2 + y2i * c2;
    r3 = y3r * c3 - y3i * s3; i3 = y3r * s3 + y3i * c3;
}

#define CA 0.9238795325112867f
#define CB 0.3826834323650898f
#define CR 0.7071067811865476f

__global__ __launch_bounds__(64, 18)
void pitch_kernel(const float* __restrict__ wav, float* __restrict__ out, Params p)
{
    // SH holds Z (1102 float2 = 2204 floats) during the FFT; after Phase C the
    // region is dead and the front 634 floats are reused for LA/CS1/LSB/RED.
    __shared__ __align__(16) float SH[2208];
    __shared__ __align__(16) float2 SPX[KU];          // unpacked raw rfft bins 0..102

    float2* Z   = reinterpret_cast<float2*>(SH);
    float*  LA  = SH;                 // [0,104)   alias, live after Phase C
    float*  CS1 = SH + 104;           // [104,208)
    float*  LSB = SH + 208;           // [208,632)  LPAD + NPITCH
    float*  RED = SH + 632;           // [632,634)

    const int tid = threadIdx.x;     // 0..63
    const int t   = blockIdx.x;
    const int b   = blockIdx.y;
    const float* w = wav + (size_t)b * NSAMP;
    const int base = t * HOP - (NFFT / 2);

    // ================= Phase A: load + stages d4,d3 in regs ======================
    float er[16], ei[16];
    if (base >= 0 && base + NFFT <= NSAMP) {
        const float2* src = reinterpret_cast<const float2*>(w + base);
        #pragma unroll
        for (int k = 0; k < 16; ++k) {
            float2 xv = src[tid + 64 * k];
            er[k] = xv.x; ei[k] = xv.y;
        }
    } else {
        #pragma unroll
        for (int k = 0; k < 16; ++k) {
            int n  = tid + 64 * k;
            int p0 = base + 2 * n, p1 = p0 + 1;
            p0 = p0 < 0 ? -p0 : (p0 >= NSAMP ? 2 * NSAMP - 2 - p0 : p0);
            p1 = p1 < 0 ? -p1 : (p1 >= NSAMP ? 2 * NSAMP - 2 - p1 : p1);
            er[k] = w[p0]; ei[k] = w[p1];
        }
    }

    {
        float c1, s1; __sincosf((float)tid * (-6.283185307179586f / 1024.0f), &s1, &c1);
        float c2 = c1 * c1 - s1 * s1, s2 = 2.0f * c1 * s1;
        float c3 = c1 * c2 - s1 * s2, s3 = c1 * s2 + s1 * c2;
        bfly4(er[0], ei[0], er[4], ei[4], er[8], ei[8], er[12], ei[12],
              c1, s1, c2, s2, c3, s3);
        bfly4(er[1], ei[1], er[5], ei[5], er[9], ei[9], er[13], ei[13],
              c1 * CA + s1 * CB, s1 * CA - c1 * CB,
              (c2 + s2) * CR,    (s2 - c2) * CR,
              c3 * CB + s3 * CA, s3 * CB - c3 * CA);
        bfly4(er[2], ei[2], er[6], ei[6], er[10], ei[10], er[14], ei[14],
              (c1 + s1) * CR, (s1 - c1) * CR,
              s2,            -c2,
              (s3 - c3) * CR, -(c3 + s3) * CR);
        bfly4(er[3], ei[3], er[7], ei[7], er[11], ei[11], er[15], ei[15],
              c1 * CB + s1 * CA, s1 * CB - c1 * CA,
              (s2 - c2) * CR,   -(c2 + s2) * CR,
              -c3 * CA - s3 * CB, c3 * CB - s3 * CA);

        float vc1 = c2 * c2 - s2 * s2, vs1 = 2.0f * c2 * s2;
        float vc2 = vc1 * vc1 - vs1 * vs1, vs2 = 2.0f * vc1 * vs1;
        float vc3 = vc1 * vc2 - vs1 * vs2, vs3 = vc1 * vs2 + vs1 * vc2;
        #pragma unroll
        for (int b2 = 0; b2 < 4; ++b2)
            bfly4(er[4 * b2], ei[4 * b2], er[4 * b2 + 1], ei[4 * b2 + 1],
                  er[4 * b2 + 2], ei[4 * b2 + 2], er[4 * b2 + 3], ei[4 * b2 + 3],
                  vc1, vs1, vc2, vs2, vc3, vs3);
    }
    #pragma unroll
    for (int k = 0; k < 16; ++k)
        Z[PHYS(tid + 64 * k)] = make_float2(er[k], ei[k]);
    __syncthreads();

    // ================= Phase B: stages d2,d1 in regs =============================
    {
        const int H  = tid >> 2;
        const int d0 = tid & 3;
        const int h  = 4 * (H & 3) + (H >> 2);
        float fr[16], fi[16];     // index 4*d2 + d1
        #pragma unroll
        for (int d2 = 0; d2 < 4; ++d2)
            #pragma unroll
            for (int d1 = 0; d1 < 4; ++d1) {
                float2 v = Z[PHYS(64 * H + 16 * d2 + 4 * d1 + d0)];
                fr[4 * d2 + d1] = v.x; fi[4 * d2 + d1] = v.y;
            }

        // W64^d0 for d0 in {0..3}: compile-time constants, selected by d0
        float uc1 = (d0 == 0) ? 1.0f
                  : (d0 == 1) ? 0.99518472667219688624f
                  : (d0 == 2) ? 0.98078528040323044913f
                              : 0.95694033573220886494f;
        float us1 = (d0 == 0) ? 0.0f
                  : (d0 == 1) ? -0.09801714032956060199f
                  : (d0 == 2) ? -0.19509032201612826785f
                              : -0.29028467725446236764f;

        #pragma unroll
        for (int d1 = 0; d1 < 4; ++d1) {
            float bc1, bs1;
            if (d1 == 0)      { bc1 = uc1; bs1 = us1; }
            else if (d1 == 1) { bc1 = uc1 * CA + us1 * CB; bs1 = us1 * CA - uc1 * CB; }
            else if (d1 == 2) { bc1 = (uc1 + us1) * CR;    bs1 = (us1 - uc1) * CR; }
            else              { bc1 = uc1 * CB + us1 * CA; bs1 = us1 * CB - uc1 * CA; }
            float bc2 = bc1 * bc1 - bs1 * bs1, bs2 = 2.0f * bc1 * bs1;
            float bc3 = bc1 * bc2 - bs1 * bs2, bs3 = bc1 * bs2 + bs1 * bc2;
            bfly4(fr[d1], fi[d1], fr[4 + d1], fi[4 + d1],
                  fr[8 + d1], fi[8 + d1], fr[12 + d1], fi[12 + d1],
                  bc1, bs1, bc2, bs2, bc3, bs3);
        }
        {
            float q2c = uc1 * uc1 - us1 * us1, q2s = 2.0f * uc1 * us1;
            float tc1 = q2c * q2c - q2s * q2s, ts1 = 2.0f * q2c * q2s;
            float tc2 = tc1 * tc1 - ts1 * ts1, ts2 = 2.0f * tc1 * ts1;
            float tc3 = tc1 * tc2 - ts1 * ts2, ts3 = tc1 * ts2 + ts1 * tc2;
            #pragma unroll
            for (int d2 = 0; d2 < 4; ++d2)
                bfly4(fr[4 * d2], fi[4 * d2], fr[4 * d2 + 1], fi[4 * d2 + 1],
                      fr[4 * d2 + 2], fi[4 * d2 + 2], fr[4 * d2 + 3], fi[4 * d2 + 3],
                      tc1, ts1, tc2, ts2, tc3, ts3);
        }

        __syncthreads();    // all PHYS reads complete before relayout rewrite

        // writeback bin-indexed: final bin row of butterfly B=16H+4d2+d1 is
        // r = 16W + h with W = 4*d1 + d2. Element c=d0 at 277*d0 + 17W + h.
        // Liveness (r<=102 or r>=154): W 7,8 dead; W6 needs h<=6; W9 needs h>=10.
        #pragma unroll
        for (int d2 = 0; d2 < 4; ++d2)
            #pragma unroll
            for (int d1 = 0; d1 < 4; ++d1) {
                const int W = 4 * d1 + d2;
                if (W == 7 || W == 8) continue;
                bool store = true;
                if (W == 6) store = (h <= 6);
                if (W == 9) store = (h >= 10);
                if (store)
                    Z[277 * d0 + 17 * W + h] =
                        make_float2(fr[4 * d2 + d1], fi[4 * d2 + d1]);
            }
    }
    __syncthreads();

    // ========== Phase C (fused): final stage + rfft unpack -> SPX[0..102] ========
    #pragma unroll
    for (int it = 0; it < 2; ++it) {
        int k = tid + 64 * it;
        if (k < KU) {
            int ra = QROW(k);
            float2 a0 = Z[ra];
            float2 a1 = Z[ra + 277];
            float2 a2 = Z[ra + 554];
            float2 a3 = Z[ra + 831];
            float Ar = (a0.x + a2.x) + (a1.x + a3.x);
            float Ai = (a0.y + a2.y) + (a1.y + a3.y);
            float Br, Bi;
            if (k == 0) { Br = Ar; Bi = Ai; }
            else {
                int rb = QROW(256 - k);
                float2 b0 = Z[rb];
                float2 b1 = Z[rb + 277];
                float2 b2 = Z[rb + 554];
                float2 b3 = Z[rb + 831];
                float t2r = b0.x - b2.x, t2i = b0.y - b2.y;
                float t3r = b1.x - b3.x, t3i = b1.y - b3.y;
                Br = t2r - t3i; Bi = t2i + t3r;       // y3 -> bin 1024-k
            }
            float zer =  0.5f * (Ar + Br);
            float zei =  0.5f * (Ai - Bi);
            float zor =  0.5f * (Ai + Bi);
            float zoi = -0.5f * (Ar - Br);
            float sn, cs;
            __sincosf((float)k * (-3.141592653589793f / 1024.0f), &sn, &cs);
            SPX[k] = make_float2(zer + cs * zor - sn * zoi,
                                 zei + cs * zoi + sn * zor);
        }
    }
    __syncthreads();   // Z fully consumed; aliased region (LA/CS1/LSB/RED) now usable

    // ====== window as spectral conv: Xw = 0.5 X[k] - 0.25(X[k-1]+X[k+1]) ========
    #pragma unroll
    for (int it = 0; it < 2; ++it) {
        int k = tid + 64 * it;
        if (k < KLA) {
            float2 Xc = SPX[k];
            float2 Xp = SPX[k + 1];
            float2 Xm = (k == 0) ? make_float2(SPX[1].x, -SPX[1].y) : SPX[k - 1];
            float xr = 0.5f * Xc.x - 0.25f * (Xm.x + Xp.x);
            float xi = 0.5f * Xc.y - 0.25f * (Xm.y + Xp.y);
            LA[k] = __logf(sqrtf(xr * xr + xi * xi) + 1e-8f);
        }
    }
    if (tid < 2) LA[KLA + tid] = 0.f;
    // zero LS front padding (aliased over dead Z; consumed after next barriers)
    if (tid < LPAD / 4)
        reinterpret_cast<float4*>(LSB)[tid] = make_float4(0.f, 0.f, 0.f, 0.f);
    __syncthreads();

    // ================= single-pass scan (warp 0): CS1 inclusive ==================
    if (tid < 32) {
        float v0 = 0.f, v1 = 0.f, v2 = 0.f, v3 = 0.f;
        if (tid < 26) {
            float4 q = reinterpret_cast<const float4*>(LA)[tid];
            v0 = q.x; v1 = q.y; v2 = q.z; v3 = q.w;
        }
        float p1 = v0 + v1, p2 = p1 + v2, p3 = p2 + v3;
        float s = p3;
        #pragma unroll
        for (int o = 1; o < 32; o <<= 1) {
            float u = __shfl_up_sync(0xffffffffu, s, o);
            if (tid >= o) s += u;
        }
        float excl = s - p3;
        if (tid < 26)
            reinterpret_cast<float4*>(CS1)[tid] =
                make_float4(excl + v0, excl + p1, excl + p2, excl + p3);
    }
    __syncthreads();

    // ============ fine structure: 4 consecutive pitch bins per thread ============
    float lsv[4];
    {
        int4 c4 = reinterpret_cast<const int4*>(p.closest)[tid];
        int cis[4] = {c4.x, c4.y, c4.z, c4.w};
        float LA0 = LA[0];
        #pragma unroll
        for (int j = 0; j < 4; ++j) {
            int ci = cis[j];                  // 3..85
            int lo = ci - 15, hi = ci + 16;   // hi <= 101
            float sum = (lo <= 0) ? fmaf((float)(-lo), LA0, CS1[hi])
                                  : CS1[hi] - CS1[lo - 1];
            lsv[j] = __expf(LA[ci] - sum * 0.03125f);
        }
        *reinterpret_cast<float4*>(&LSB[LPAD + 4 * tid]) =
            make_float4(lsv[0], lsv[1], lsv[2], lsv[3]);
    }
    __syncthreads();

    // ================= subharmonic summation (zero-padded, guard-free) ==========
    float acc[4] = {lsv[0], lsv[1], lsv[2], lsv[3]};
    #pragma unroll
    for (int n = 1; n < 8; ++n) {
        int   sh = p.shift[n];
        float wn = p.wgt[n];
        int   bi = LPAD + 4 * tid - sh;       // >= 3 always
        if ((sh & 3) == 0) {
            float4 q = *reinterpret_cast<const float4*>(&LSB[bi]);
            acc[0] = fmaf(wn, q.x, acc[0]);
            acc[1] = fmaf(wn, q.y, acc[1]);
            acc[2] = fmaf(wn, q.z, acc[2]);
            acc[3] = fmaf(wn, q.w, acc[3]);
        } else if ((sh & 1) == 0) {
            float2 qa = *reinterpret_cast<const float2*>(&LSB[bi]);
            float2 qb = *reinterpret_cast<const float2*>(&LSB[bi + 2]);
            acc[0] = fmaf(wn, qa.x, acc[0]);
            acc[1] = fmaf(wn, qa.y, acc[1]);
            acc[2] = fmaf(wn, qb.x, acc[2]);
            acc[3] = fmaf(wn, qb.y, acc[3]);
        } else {
            #pragma unroll
            for (int j = 0; j < 4; ++j)
                acc[j] = fmaf(wn, LSB[bi + j], acc[j]);
        }
    }

    // ================= per-frame max, normalize, store ===========================
    float mloc = fmaxf(fmaxf(acc[0], acc[1]), fmaxf(acc[2], acc[3]));
    #pragma unroll
    for (int o = 16; o; o >>= 1)
        mloc = fmaxf(mloc, __shfl_xor_sync(0xffffffffu, mloc, o));
    if ((tid & 31) == 0) RED[tid >> 5] = mloc;
    __syncthreads();
    float mx = fmaxf(fmaxf(RED[0], RED[1]), 1e-8f);

    float4 o4;
    o4.x = __fdividef(acc[0], mx);
    o4.y = __fdividef(acc[1], mx);
    o4.z = __fdividef(acc[2], mx);
    o4.w = __fdividef(acc[3], mx);
    reinterpret_cast<float4*>(out + ((size_t)b * TFRAMES + t) * NPITCH)[tid] = o4;
}

extern "C" void kernel_launch(void* const* d_in, const int* in_sizes, int n_in,
                              void* d_out, int out_size)
{
    (void)in_sizes; (void)n_in; (void)out_size;
    const float* wav = (const float*)d_in[0];
    float* out = (float*)d_out;

    Params p;

    // Gather indices: f32 argmin over |linspace(0,12000,1025) - center_freq|
    const double l40 = log(40.0), l1000 = log(1000.0);
    for (int j = 0; j < NPITCH; ++j) {
        double cd = exp(l40 + (double)j * (l1000 - l40) / 255.0);
        float  cf = (float)cd;
        const float step = 11.71875f;
        int i0 = (int)(cd / 11.71875);
        int best = 0; float bestd = 3.4e38f;
        for (int i = i0 - 2; i <= i0 + 2; ++i) {
            int ic = i < 0 ? 0 : (i > 1024 ? 1024 : i);
            float d = fabsf((float)ic * step - cf);
            if (d < bestd) { bestd = d; best = ic; }
        }
        p.closest[j] = best;
    }

    // Harmonic shifts: Python round() == rint (half-even), identical expression
    const double cpb = 1200.0 * log2(25.0) / 255.0;
    p.shift[0] = 0; p.wgt[0] = 1.0f;
    for (int n = 2; n <= 8; ++n) {
        p.shift[n - 1] = (int)rint(1200.0 * log2((double)n) / cpb);
        p.wgt[n - 1]   = (float)pow(0.86, (double)(n - 1));
    }

    dim3 grid(TFRAMES, BATCH);
    pitch_kernel<<<grid, 64>>>(wav, out, p);
}